// round 17
// baseline (speedup 1.0000x reference)
#include <cuda_runtime.h>
#include <cuda_fp16.h>
#include <cstdint>

// CapsuleLayer: conv(stride2,3x3) via mma.sync fp16 (m16n8k16, fp32 accum,
// ldmatrix loads, 64x64 warp tiles), u_hat fp16, 3x dynamic routing (fp32),
// fused final route+transpose.
// x: [8,8,32,64,64] fp32   W: [512,32,3,3]   bias: [512]
// out: [8,8,64,32,32] (N,T1,Z1,H1,W1) fp32

#define DEVINL __device__ __forceinline__

DEVINL uint32_t smem_u32(const void* p) {
    uint32_t a;
    asm("{ .reg .u64 t; cvta.to.shared.u64 t, %1; cvt.u32.u64 %0, t; }" : "=r"(a) : "l"(p));
    return a;
}
DEVINL void cp16(uint32_t dst, const void* src) {
    asm volatile("cp.async.cg.shared.global [%0], [%1], 16;" ::"r"(dst), "l"(src) : "memory");
}
DEVINL uint32_t h2u(__half2 h) { return *reinterpret_cast<uint32_t*>(&h); }
DEVINL float2 u2f(uint32_t u) {
    __half2 h = *reinterpret_cast<__half2*>(&u);
    return __half22float2(h);
}
DEVINL void ldmx4(uint32_t& r0, uint32_t& r1, uint32_t& r2, uint32_t& r3, uint32_t addr) {
    asm volatile("ldmatrix.sync.aligned.m8n8.x4.shared.b16 {%0,%1,%2,%3}, [%4];"
                 : "=r"(r0), "=r"(r1), "=r"(r2), "=r"(r3) : "r"(addr));
}

// ---------------------------------------------------------------------------
__device__ __align__(128) __half g_xh[64 * 66 * 66 * 32];        // NHWC padded, fp16
__device__ __align__(128) __half g_wh[9 * 512 * 32];             // [kpos][oc][ic], fp16
__device__ __align__(128) __half g_u2h[8 * 32 * 32 * 8 * 8 * 64];// [n][h][w][t0][t1][z] fp16
__device__ __align__(128) float g_b [8 * 8 * 32 * 32 * 8];       // [n][t0][h][w][t1]
__device__ __align__(128) float g_r [8 * 8 * 32 * 32 * 8];

// ---------------------------------------------------------------------------
// 1) x -> g_xh  (NCHW -> padded NHWC, fp16)
// ---------------------------------------------------------------------------
__global__ __launch_bounds__(256) void xt_kernel(const float* __restrict__ x) {
    __shared__ float s[64 * 33];
    const int b = blockIdx.y, h0 = blockIdx.x;
    const int t = threadIdx.x;
    const int lane = t & 31, icg = t >> 5;
    const float* xp = x + ((size_t)(b * 32) * 64 + h0) * 64;
#pragma unroll
    for (int i = 0; i < 4; i++) {
        int ic = icg + 8 * i;
        s[lane * 33 + ic]        = xp[(size_t)ic * 4096 + lane];
        s[(lane + 32) * 33 + ic] = xp[(size_t)ic * 4096 + lane + 32];
    }
    __syncthreads();
    __half2* dst = (__half2*)(g_xh + (((size_t)b * 66 + h0 + 1) * 66 + 1) * 32);
#pragma unroll
    for (int i = 0; i < 4; i++) {
        int idx = t + 256 * i;              // 1024 half2 = 64 px * 16 pairs
        int w0 = idx >> 4, icp = idx & 15;
        dst[w0 * 16 + icp] = __floats2half2_rn(s[w0 * 33 + 2 * icp],
                                               s[w0 * 33 + 2 * icp + 1]);
    }
}

// ---------------------------------------------------------------------------
// 2) W -> g_wh [kpos][oc][ic] fp16
// ---------------------------------------------------------------------------
__global__ void w2_kernel(const float* __restrict__ W) {
    int idx = blockIdx.x * 256 + threadIdx.x;   // oc*288 + ic*9 + kp
    if (idx >= 512 * 288) return;
    int oc = idx / 288, r = idx % 288, ic = r / 9, kp = r % 9;
    g_wh[((size_t)kp * 512 + oc) * 32 + ic] = __float2half_rn(W[idx]);
}

// ---------------------------------------------------------------------------
// 3) conv: CTA = 128 oc x 256 px (8 rows), warp tile 64x64, 8 warps.
//    A tile 10KB, B tile 20KB, double-buffered (60KB); epilogue staged in
//    two 128-px passes.  B fragments via PAIRED ldmx4 (2 ni per instr).
// ---------------------------------------------------------------------------
#define RSTRB 80
#define ATILE_B (128 * RSTRB)        // 10240
#define BTILE_B (256 * RSTRB)        // 20480
#define AOFF0 0u
#define BOFF0 10240u
#define AOFF1 30720u
#define BOFF1 40960u
#define CONV_SMEM 67584              // epilogue stage 128*132*4

__global__ __launch_bounds__(256, 1) void conv_mma_kernel(const float* __restrict__ bias) {
    extern __shared__ float dsm[];
    const uint32_t sbase = smem_u32(dsm);
    const uint32_t offA[2] = {AOFF0, AOFF1};
    const uint32_t offB[2] = {BOFF0, BOFF1};

    const int tid = threadIdx.x;
    const int wid = tid >> 5, lane = tid & 31;
    const int gid = lane >> 2, tig = lane & 3;

    const int pt = blockIdx.x;    // 8 output rows
    const int m  = blockIdx.y;    // oc block of 128
    const int b  = blockIdx.z;    // n*8 + t0
    const int h0 = pt * 8;

    const int m0 = (wid & 1) * 64;
    const int ng = wid >> 1;             // n-group 0..3
    const int n0 = ng * 64;

    // ldmatrix lane-address offsets (bytes within tile)
    uint32_t aoff[4], boff[4];
#pragma unroll
    for (int mi = 0; mi < 4; mi++)
        aoff[mi] = (uint32_t)((m0 + mi * 16 + (lane & 15)) * RSTRB + (lane >> 4) * 16);
#pragma unroll
    for (int np = 0; np < 4; np++)
        boff[np] = (uint32_t)((n0 + np * 16 + (lane & 7) + ((lane >> 4) & 1) * 8) * RSTRB
                              + ((lane >> 3) & 1) * 16);

    float acc[4][8][4];
#pragma unroll
    for (int mi = 0; mi < 4; mi++)
#pragma unroll
        for (int ni = 0; ni < 8; ni++)
#pragma unroll
            for (int j = 0; j < 4; j++) acc[mi][ni][j] = 0.f;

    auto issue = [&](int s, int buf) {
        const int kh = s / 3, kw = s % 3;
        const uint4* Asrc = (const uint4*)g_wh + ((size_t)s * 512 + m * 128) * 4;
        const int ihb = 2 * h0 + kh;
#pragma unroll
        for (int i = 0; i < 2; i++) {        // A: 512 chunks
            int c = tid + 256 * i;
            int o = c >> 2, q = c & 3;
            cp16(sbase + offA[buf] + o * RSTRB + q * 16, Asrc + c);
        }
#pragma unroll
        for (int i = 0; i < 4; i++) {        // B: 1024 chunks (256 px)
            int c = tid + 256 * i;
            int o = c >> 2, q = c & 3;
            int hl = o >> 5, wl = o & 31;
            const uint4* src =
                (const uint4*)g_xh + (((size_t)b * 66 + ihb + 2 * hl) * 66 + 2 * wl + kw) * 4 + q;
            cp16(sbase + offB[buf] + o * RSTRB + q * 16, src);
        }
        asm volatile("cp.async.commit_group;");
    };

    issue(0, 0);

    for (int s = 0; s < 9; s++) {
        if (s < 8) {
            issue(s + 1, (s + 1) & 1);
            asm volatile("cp.async.wait_group 1;" ::: "memory");
        } else {
            asm volatile("cp.async.wait_group 0;" ::: "memory");
        }
        __syncthreads();

        const uint32_t aA = sbase + offA[s & 1];
        const uint32_t aB = sbase + offB[s & 1];

#pragma unroll
        for (int kk = 0; kk < 2; kk++) {
            const uint32_t ko = kk * 32;
            uint32_t a[4][4];
#pragma unroll
            for (int mi = 0; mi < 4; mi++)
                ldmx4(a[mi][0], a[mi][1], a[mi][2], a[mi][3], aA + aoff[mi] + ko);
            uint32_t bf[8][2];
#pragma unroll
            for (int np = 0; np < 4; np++)
                ldmx4(bf[2 * np][0], bf[2 * np][1], bf[2 * np + 1][0], bf[2 * np + 1][1],
                      aB + boff[np] + ko);
#pragma unroll
            for (int mi = 0; mi < 4; mi++)
#pragma unroll
                for (int ni = 0; ni < 8; ni++)
                    asm volatile(
                        "mma.sync.aligned.m16n8k16.row.col.f32.f16.f16.f32 "
                        "{%0,%1,%2,%3}, {%4,%5,%6,%7}, {%8,%9}, {%0,%1,%2,%3};"
                        : "+f"(acc[mi][ni][0]), "+f"(acc[mi][ni][1]),
                          "+f"(acc[mi][ni][2]), "+f"(acc[mi][ni][3])
                        : "r"(a[mi][0]), "r"(a[mi][1]), "r"(a[mi][2]), "r"(a[mi][3]),
                          "r"(bf[ni][0]), "r"(bf[ni][1]));
        }
        __syncthreads();
    }

    // Epilogue: two 128-px passes through stage[128][132] (+bias) -> g_u2h
    float* stage = dsm;
    const int n = b >> 3, t0 = b & 7;
#pragma unroll 1
    for (int ph = 0; ph < 2; ph++) {
        if ((ng >> 1) == ph) {
            const int n0l = (ng & 1) * 64;   // pixel base within this pass
#pragma unroll
            for (int mi = 0; mi < 4; mi++) {
                int r = m0 + mi * 16 + gid;
                float bi0 = bias[m * 128 + r];
                float bi1 = bias[m * 128 + r + 8];
#pragma unroll
                for (int ni = 0; ni < 8; ni++) {
                    int cn = n0l + ni * 8 + 2 * tig;
                    stage[cn * 132 + r]           = acc[mi][ni][0] + bi0;
                    stage[(cn + 1) * 132 + r]     = acc[mi][ni][1] + bi0;
                    stage[cn * 132 + r + 8]       = acc[mi][ni][2] + bi1;
                    stage[(cn + 1) * 132 + r + 8] = acc[mi][ni][3] + bi1;
                }
            }
        }
        __syncthreads();
#pragma unroll
        for (int k = 0; k < 8; k++) {
            int idx = tid + 256 * k;            // 2048 chunks of 8 oc
            int p = idx >> 4, q = idx & 15;
            int gp = ph * 128 + p;
            int h = h0 + (gp >> 5), w = gp & 31;
            float4 v0 = *(const float4*)(stage + p * 132 + q * 8);
            float4 v1 = *(const float4*)(stage + p * 132 + q * 8 + 4);
            uint4 pk;
            pk.x = h2u(__floats2half2_rn(v0.x, v0.y));
            pk.y = h2u(__floats2half2_rn(v0.z, v0.w));
            pk.z = h2u(__floats2half2_rn(v1.x, v1.y));
            pk.w = h2u(__floats2half2_rn(v1.z, v1.w));
            size_t off = ((((size_t)(n * 32 + h) * 32 + w) * 8 + t0) * 512) + m * 128 + q * 8;
            *(uint4*)(g_u2h + off) = pk;
        }
        __syncthreads();
    }
}

// ---------------------------------------------------------------------------
// 4) Routing iterations 0/1: 2 pixels per block, 64 threads each.
// ---------------------------------------------------------------------------
template <int MODE>
__global__ __launch_bounds__(128) void route_kernel() {
    __shared__ float sr[128];           // [ph][t0*8+t1]

    const int tid = threadIdx.x;
    const int ph = tid >> 6;
    const int pix = blockIdx.x * 2 + ph;
    const int n = pix >> 10;
    const int hw = pix & 1023;
    const int lt = tid & 63;
    const int t1 = lt >> 3;
    const int z8 = lt & 7;

    if (MODE >= 1) {
        int rt0 = lt >> 3, rt1 = lt & 7;
        sr[ph * 64 + rt0 * 8 + rt1] = g_r[((n * 8 + rt0) * 1024 + hw) * 8 + rt1];
    }

    uint4 uu[8];
    const uint4* up = (const uint4*)g_u2h + (size_t)pix * 512 + t1 * 8 + z8;
#pragma unroll
    for (int t0 = 0; t0 < 8; t0++) uu[t0] = up[t0 * 64];

    if (MODE >= 1) __syncthreads();

    float p[8];
#pragma unroll
    for (int j = 0; j < 8; j++) p[j] = 0.f;
#pragma unroll
    for (int t0 = 0; t0 < 8; t0++) {
        float r = (MODE == 0) ? 0.125f : sr[ph * 64 + t0 * 8 + t1];
        float2 f0 = u2f(uu[t0].x), f1 = u2f(uu[t0].y);
        float2 f2 = u2f(uu[t0].z), f3 = u2f(uu[t0].w);
        p[0] += r * f0.x; p[1] += r * f0.y; p[2] += r * f1.x; p[3] += r * f1.y;
        p[4] += r * f2.x; p[5] += r * f2.y; p[6] += r * f3.x; p[7] += r * f3.y;
    }
    float n2 = 0.f;
#pragma unroll
    for (int j = 0; j < 8; j++) n2 += p[j] * p[j];
#pragma unroll
    for (int mm = 1; mm < 8; mm <<= 1) n2 += __shfl_xor_sync(0xffffffffu, n2, mm);
    float s = n2 / (1.f + n2) * rsqrtf(n2 + 1e-9f);
    float v[8];
#pragma unroll
    for (int j = 0; j < 8; j++) v[j] = p[j] * s;

    float d[8];
#pragma unroll
    for (int t0 = 0; t0 < 8; t0++) {
        float2 f0 = u2f(uu[t0].x), f1 = u2f(uu[t0].y);
        float2 f2 = u2f(uu[t0].z), f3 = u2f(uu[t0].w);
        d[t0] = f0.x * v[0] + f0.y * v[1] + f1.x * v[2] + f1.y * v[3] +
                f2.x * v[4] + f2.y * v[5] + f3.x * v[6] + f3.y * v[7];
    }
#pragma unroll
    for (int mm = 1; mm < 8; mm <<= 1) {
#pragma unroll
        for (int t0 = 0; t0 < 8; t0++)
            d[t0] += __shfl_xor_sync(0xffffffffu, d[t0], mm);
    }
    if (z8 == 0) {
#pragma unroll
        for (int t0 = 0; t0 < 8; t0++) {
            float* bp = &g_b[((n * 8 + t0) * 1024 + hw) * 8 + t1];
            if (MODE == 0) *bp = d[t0];
            else           *bp += d[t0];
        }
    }
}

// ---------------------------------------------------------------------------
// 5) r = softmax_t1(maxpool3x3(b)).  grid (band=4, nt=64), 256 thr, h-banded.
// ---------------------------------------------------------------------------
__global__ __launch_bounds__(256) void pool_softmax_kernel() {
    __shared__ float sb[10 * 32 * 8];
    const int band = blockIdx.x, nt = blockIdx.y;
    const int tid = threadIdx.x;
    const int h_base = band * 8 - 1;

    for (int i = tid; i < 640; i += 256) {
        int lr = i >> 6, rem = i & 63;
        int gh = h_base + lr;
        float4 v;
        if (gh >= 0 && gh < 32)
            v = ((const float4*)(g_b + nt * 8192 + gh * 256))[rem];
        else
            v = make_float4(-3.4e38f, -3.4e38f, -3.4e38f, -3.4e38f);
        ((float4*)sb)[i] = v;
    }
    __syncthreads();

    const int hl = tid >> 5, w = tid & 31;
    float m[8];
#pragma unroll
    for (int t = 0; t < 8; t++) m[t] = -3.4e38f;
#pragma unroll
    for (int dh = 0; dh < 3; dh++) {
        int lr = hl + dh;
#pragma unroll
        for (int dw = -1; dw <= 1; dw++) {
            int ww = w + dw;
            if (ww < 0 || ww > 31) continue;
            const float* pp = &sb[(lr * 32 + ww) * 8];
#pragma unroll
            for (int t = 0; t < 8; t++) m[t] = fmaxf(m[t], pp[t]);
        }
    }
    float mx = m[0];
#pragma unroll
    for (int t = 1; t < 8; t++) mx = fmaxf(mx, m[t]);
    float e[8], ssum = 0.f;
#pragma unroll
    for (int t = 0; t < 8; t++) { e[t] = expf(m[t] - mx); ssum += e[t]; }
    float inv = 1.f / ssum;
    float* dst = &g_r[nt * 8192 + ((band * 8 + hl) * 32 + w) * 8];
    *(float4*)(dst + 0) = make_float4(e[0] * inv, e[1] * inv, e[2] * inv, e[3] * inv);
    *(float4*)(dst + 4) = make_float4(e[4] * inv, e[5] * inv, e[6] * inv, e[7] * inv);
}

// ---------------------------------------------------------------------------
// 6) Final routing iteration fused with transpose.
//    Block = 8 pixels of one (n,h) row; 256 thr = 4 pixel-slots x 64, 2 iters.
// ---------------------------------------------------------------------------
__global__ __launch_bounds__(256) void route2t_kernel(float* __restrict__ out) {
    __shared__ float vt[8 * 516];
    const int wq = blockIdx.x;          // quarter-row
    const int h  = blockIdx.y;
    const int n  = blockIdx.z;
    const int tid = threadIdx.x;
    const int slot = tid >> 6;          // 0..3
    const int lt = tid & 63;
    const int t1 = lt >> 3;
    const int z8 = lt & 7;
    const int w0 = wq * 8;

#pragma unroll
    for (int wp = 0; wp < 2; wp++) {
        const int wl = wp * 4 + slot;   // 0..7
        const int w = w0 + wl;
        const int hw = h * 32 + w;
        const int pix = (n * 32 + h) * 32 + w;

        float r[8];
#pragma unroll
        for (int t0 = 0; t0 < 8; t0++)
            r[t0] = g_r[((n * 8 + t0) * 1024 + hw) * 8 + t1];

        float p[8];
#pragma unroll
        for (int j = 0; j < 8; j++) p[j] = 0.f;
        const uint4* up = (const uint4*)g_u2h + (size_t)pix * 512 + t1 * 8 + z8;
#pragma unroll
        for (int t0 = 0; t0 < 8; t0++) {
            uint4 uu = up[t0 * 64];
            float2 f0 = u2f(uu.x), f1 = u2f(uu.y), f2 = u2f(uu.z), f3 = u2f(uu.w);
            p[0] += r[t0] * f0.x; p[1] += r[t0] * f0.y;
            p[2] += r[t0] * f1.x; p[3] += r[t0] * f1.y;
            p[4] += r[t0] * f2.x; p[5] += r[t0] * f2.y;
            p[6] += r[t0] * f3.x; p[7] += r[t0] * f3.y;
        }
        float n2 = 0.f;
#pragma unroll
        for (int j = 0; j < 8; j++) n2 += p[j] * p[j];
#pragma unroll
        for (int mm = 1; mm < 8; mm <<= 1) n2 += __shfl_xor_sync(0xffffffffu, n2, mm);
        float s = n2 / (1.f + n2) * rsqrtf(n2 + 1e-9f);

        float* vp = &vt[wl * 516 + t1 * 64 + z8 * 8];
        *(float4*)(vp + 0) = make_float4(p[0] * s, p[1] * s, p[2] * s, p[3] * s);
        *(float4*)(vp + 4) = make_float4(p[4] * s, p[5] * s, p[6] * s, p[7] * s);
    }
    __syncthreads();

    float* dst = out + (size_t)n * 512 * 1024 + h * 32 + w0;
#pragma unroll
    for (int k = 0; k < 8; k++) {
        int idx = tid + 256 * k;            // 0..2047 float2 slots
        int row = idx >> 2, col2 = idx & 3; // 512 rows x 4 float2-cols
        float2 v2 = make_float2(vt[(col2 * 2 + 0) * 516 + row],
                                vt[(col2 * 2 + 1) * 516 + row]);
        *(float2*)(dst + (size_t)row * 1024 + col2 * 2) = v2;
    }
}

// ---------------------------------------------------------------------------
extern "C" void kernel_launch(void* const* d_in, const int* in_sizes, int n_in,
                              void* d_out, int out_size) {
    const float* x    = (const float*)d_in[0];
    const float* W    = (const float*)d_in[1];
    const float* bias = (const float*)d_in[2];
    float* out = (float*)d_out;

    cudaFuncSetAttribute(conv_mma_kernel,
                         cudaFuncAttributeMaxDynamicSharedMemorySize, CONV_SMEM);

    xt_kernel<<<dim3(64, 64), 256>>>(x);
    w2_kernel<<<576, 256>>>(W);
    conv_mma_kernel<<<dim3(4, 4, 64), 256, CONV_SMEM>>>(bias);

    route_kernel<0><<<4096, 128>>>();
    pool_softmax_kernel<<<dim3(4, 64), 256>>>();
    route_kernel<1><<<4096, 128>>>();
    pool_softmax_kernel<<<dim3(4, 64), 256>>>();
    route2t_kernel<<<dim3(4, 32, 8), 256>>>(out);
}